// round 2
// baseline (speedup 1.0000x reference)
#include <cuda_runtime.h>
#include <math.h>

#define HEADS 8
#define DH    64
#define NQ    4096
#define NK    1024
#define BATCH 2
#define D     512
#define DC    768
#define BH    (BATCH*HEADS)   // 16
#define MQ    (BATCH*NQ)      // 8192 rows of q
#define MK    (BATCH*NK)      // 2048 rows of k/v

// ---------------- scratch (device globals; no allocation allowed) ----------------
__device__ float g_q[MQ*D];            // q projection fp32
__device__ float g_k[MK*D];            // k projection fp32
__device__ float g_v[MK*D];            // v projection fp32
__device__ float g_oattn[MQ*D];        // attention output (pre out-proj)
__device__ int   g_q8 [BH*NQ*16];      // [bh][n][w]   int packs q8 dims 4w..4w+3
__device__ int   g_k8t[BH*16*NK];      // [bh][w][j]   int packs k8 dims 4w..4w+3 of row j
__device__ int   g_v8t[BH*256*DH];     // [bh][w][d]   int packs v8 rows j=4w..4w+3 of dim d
__device__ float g_rowmax[BH*NQ];
__device__ float g_rowz  [BH*NQ];
__device__ int   g_maxbits[4];         // abs-max bits: 0:q 1:k 2:v 3:attn(=max 1/Z)

// ---------------- init ----------------
__global__ void init_kernel() {
    if (threadIdx.x < 4) g_maxbits[threadIdx.x] = 0;
}

// ---------------- fp32 GEMM: C[M,N] = A[M,K] @ B[K,N] (+bias) ----------------
// 128x128 tile, BK=8, 256 threads, 8x8 per-thread microtile.
__global__ __launch_bounds__(256) void gemm128(
    const float* __restrict__ A, const float* __restrict__ B,
    const float* __restrict__ bias, float* __restrict__ C,
    int M, int N, int K)
{
    __shared__ float As[8][128];
    __shared__ float Bs[8][128];
    const int tid  = threadIdx.x;
    const int tx   = tid & 15;
    const int ty   = tid >> 4;
    const int row0 = blockIdx.y * 128;
    const int col0 = blockIdx.x * 128;

    const int am = tid >> 1;          // 0..127
    const int ak = (tid & 1) * 4;     // 0 or 4
    const int bk = tid >> 5;          // 0..7
    const int bn = (tid & 31) * 4;    // 0..124

    float acc[8][8];
    #pragma unroll
    for (int i = 0; i < 8; i++)
        #pragma unroll
        for (int j = 0; j < 8; j++) acc[i][j] = 0.0f;

    for (int k0 = 0; k0 < K; k0 += 8) {
        float4 a4 = *(const float4*)(A + (size_t)(row0 + am) * K + k0 + ak);
        float4 b4 = *(const float4*)(B + (size_t)(k0 + bk) * N + col0 + bn);
        As[ak + 0][am] = a4.x;
        As[ak + 1][am] = a4.y;
        As[ak + 2][am] = a4.z;
        As[ak + 3][am] = a4.w;
        *(float4*)(&Bs[bk][bn]) = b4;
        __syncthreads();
        #pragma unroll
        for (int kk = 0; kk < 8; kk++) {
            float4 a0 = *(const float4*)(&As[kk][ty * 8]);
            float4 a1 = *(const float4*)(&As[kk][ty * 8 + 4]);
            float4 b0 = *(const float4*)(&Bs[kk][tx * 8]);
            float4 b1 = *(const float4*)(&Bs[kk][tx * 8 + 4]);
            float a[8] = {a0.x, a0.y, a0.z, a0.w, a1.x, a1.y, a1.z, a1.w};
            float b[8] = {b0.x, b0.y, b0.z, b0.w, b1.x, b1.y, b1.z, b1.w};
            #pragma unroll
            for (int i = 0; i < 8; i++)
                #pragma unroll
                for (int j = 0; j < 8; j++)
                    acc[i][j] = fmaf(a[i], b[j], acc[i][j]);
        }
        __syncthreads();
    }

    #pragma unroll
    for (int i = 0; i < 8; i++) {
        const int r = row0 + ty * 8 + i;
        #pragma unroll
        for (int j = 0; j < 8; j += 4) {
            const int c = col0 + tx * 8 + j;
            float4 o;
            o.x = acc[i][j + 0];
            o.y = acc[i][j + 1];
            o.z = acc[i][j + 2];
            o.w = acc[i][j + 3];
            if (bias) {
                o.x += bias[c + 0]; o.y += bias[c + 1];
                o.z += bias[c + 2]; o.w += bias[c + 3];
            }
            *(float4*)(C + (size_t)r * N + c) = o;
        }
    }
}

// ---------------- abs-max reduction (atomicMax on positive float bits) ----------------
__global__ void absmax_kernel(const float* __restrict__ x, int n, int slot) {
    float m = 0.0f;
    for (int i = blockIdx.x * blockDim.x + threadIdx.x; i < n; i += gridDim.x * blockDim.x)
        m = fmaxf(m, fabsf(x[i]));
    #pragma unroll
    for (int o = 16; o; o >>= 1) m = fmaxf(m, __shfl_xor_sync(0xffffffffu, m, o));
    __shared__ float sm[8];
    if ((threadIdx.x & 31) == 0) sm[threadIdx.x >> 5] = m;
    __syncthreads();
    if (threadIdx.x == 0) {
        float mm = sm[0];
        #pragma unroll
        for (int i = 1; i < 8; i++) mm = fmaxf(mm, sm[i]);
        atomicMax(&g_maxbits[slot], __float_as_int(mm));
    }
}

__device__ __forceinline__ int quant1(float v, float invd) {
    int q = __float2int_rn(v * invd);       // round-to-nearest-even, matches jnp.round
    q = max(-128, min(127, q));
    return q & 0xff;
}
__device__ __forceinline__ int pack4(float a, float b, float c, float d, float invd) {
    return quant1(a, invd) | (quant1(b, invd) << 8) |
           (quant1(c, invd) << 16) | (quant1(d, invd) << 24);
}

// ---------------- quantize q: [bh][n][16 words of 4 dims] ----------------
__global__ void quant_q_kernel() {
    int tid = blockIdx.x * blockDim.x + threadIdx.x;   // BH*NQ*16 = 2^20
    int dw = tid & 15;
    int n  = (tid >> 4) & (NQ - 1);
    int bh = tid >> 16;
    int b = bh >> 3, h = bh & 7;
    float invd = 127.0f / __int_as_float(g_maxbits[0]);
    float4 v = *(const float4*)(g_q + ((size_t)(b * NQ + n) * D + h * DH + dw * 4));
    g_q8[tid] = pack4(v.x, v.y, v.z, v.w, invd);
}

// ---------------- quantize k transposed: [bh][w][j] ----------------
__global__ void quant_kT_kernel() {
    int tid = blockIdx.x * blockDim.x + threadIdx.x;   // BH*16*NK = 2^18
    int j  = tid & (NK - 1);
    int w  = (tid >> 10) & 15;
    int bh = tid >> 14;
    int b = bh >> 3, h = bh & 7;
    float invd = 127.0f / __int_as_float(g_maxbits[1]);
    float4 v = *(const float4*)(g_k + ((size_t)(b * NK + j) * D + h * DH + w * 4));
    g_k8t[tid] = pack4(v.x, v.y, v.z, v.w, invd);
}

// ---------------- quantize v transposed: [bh][w=j/4][d] ----------------
__global__ void quant_vT_kernel() {
    int tid = blockIdx.x * blockDim.x + threadIdx.x;   // BH*256*64 = 2^18
    int d  = tid & 63;
    int w  = (tid >> 6) & 255;
    int bh = tid >> 14;
    int b = bh >> 3, h = bh & 7;
    float invd = 127.0f / __int_as_float(g_maxbits[2]);
    int j0 = w * 4;
    float v0 = g_v[(size_t)(b * NK + j0 + 0) * D + h * DH + d];
    float v1 = g_v[(size_t)(b * NK + j0 + 1) * D + h * DH + d];
    float v2 = g_v[(size_t)(b * NK + j0 + 2) * D + h * DH + d];
    float v3 = g_v[(size_t)(b * NK + j0 + 3) * D + h * DH + d];
    g_v8t[tid] = pack4(v0, v1, v2, v3, invd);
}

// ---------------- attention pass 1: scores + softmax stats + global attn-max ----------------
// One warp per q row, 8 rows/block. Lane handles 4 consecutive j per t-group (int4 loads).
__global__ __launch_bounds__(256) void attn_pass1() {
    const int lane = threadIdx.x & 31;
    const int warp = threadIdx.x >> 5;
    const int bh   = blockIdx.y;
    const int row  = blockIdx.x * 8 + warp;
    const float dq = __int_as_float(g_maxbits[0]) * (1.0f / 127.0f);
    const float dk = __int_as_float(g_maxbits[1]) * (1.0f / 127.0f);
    const float alpha = dq * dk * 0.125f;   // * dh^-0.5

    int q[16];
    const int* qr = g_q8 + ((size_t)bh * NQ + row) * 16;
    #pragma unroll
    for (int i = 0; i < 16; i++) q[i] = qr[i];

    const int* kb = g_k8t + (size_t)bh * 16 * NK;
    float sim[32];
    float rmax = -1e30f;
    #pragma unroll
    for (int t = 0; t < 8; t++) {
        int s0 = 0, s1 = 0, s2 = 0, s3 = 0;
        const int jbase = t * 128 + lane * 4;
        #pragma unroll
        for (int w = 0; w < 16; w++) {
            int4 kv = *(const int4*)(kb + w * NK + jbase);
            s0 = __dp4a(q[w], kv.x, s0);
            s1 = __dp4a(q[w], kv.y, s1);
            s2 = __dp4a(q[w], kv.z, s2);
            s3 = __dp4a(q[w], kv.w, s3);
        }
        sim[t * 4 + 0] = (float)s0 * alpha;
        sim[t * 4 + 1] = (float)s1 * alpha;
        sim[t * 4 + 2] = (float)s2 * alpha;
        sim[t * 4 + 3] = (float)s3 * alpha;
        rmax = fmaxf(rmax, fmaxf(fmaxf(sim[t*4], sim[t*4+1]), fmaxf(sim[t*4+2], sim[t*4+3])));
    }
    #pragma unroll
    for (int o = 16; o; o >>= 1) rmax = fmaxf(rmax, __shfl_xor_sync(0xffffffffu, rmax, o));
    float z = 0.0f;
    #pragma unroll
    for (int t = 0; t < 32; t++) z += expf(sim[t] - rmax);
    #pragma unroll
    for (int o = 16; o; o >>= 1) z += __shfl_xor_sync(0xffffffffu, z, o);

    __shared__ float s_m[8];
    if (lane == 0) {
        g_rowmax[(size_t)bh * NQ + row] = rmax;
        g_rowz  [(size_t)bh * NQ + row] = z;
        s_m[warp] = 1.0f / z;               // max attn prob of this row
    }
    __syncthreads();
    if (threadIdx.x == 0) {
        float mm = s_m[0];
        #pragma unroll
        for (int i = 1; i < 8; i++) mm = fmaxf(mm, s_m[i]);
        atomicMax(&g_maxbits[3], __float_as_int(mm));
    }
}

// ---------------- attention pass 2: recompute scores, quantize attn, int8 AV ----------------
__global__ __launch_bounds__(256) void attn_pass2() {
    __shared__ int s_aq[8][256];            // packed int8 attn weights per warp-row
    const int lane = threadIdx.x & 31;
    const int warp = threadIdx.x >> 5;
    const int bh   = blockIdx.y;
    const int row  = blockIdx.x * 8 + warp;
    const int b = bh >> 3, h = bh & 7;

    const float dq = __int_as_float(g_maxbits[0]) * (1.0f / 127.0f);
    const float dk = __int_as_float(g_maxbits[1]) * (1.0f / 127.0f);
    const float alpha = dq * dk * 0.125f;
    const float amax  = __int_as_float(g_maxbits[3]);
    const float da    = amax * (1.0f / 127.0f);
    const float dv    = __int_as_float(g_maxbits[2]) * (1.0f / 127.0f);
    const float rmax  = g_rowmax[(size_t)bh * NQ + row];
    const float escale = (1.0f / g_rowz[(size_t)bh * NQ + row]) * (127.0f / amax);

    int q[16];
    const int* qr = g_q8 + ((size_t)bh * NQ + row) * 16;
    #pragma unroll
    for (int i = 0; i < 16; i++) q[i] = qr[i];

    const int* kb = g_k8t + (size_t)bh * 16 * NK;
    #pragma unroll
    for (int t = 0; t < 8; t++) {
        int s0 = 0, s1 = 0, s2 = 0, s3 = 0;
        const int jbase = t * 128 + lane * 4;
        #pragma unroll
        for (int w = 0; w < 16; w++) {
            int4 kv = *(const int4*)(kb + w * NK + jbase);
            s0 = __dp4a(q[w], kv.x, s0);
            s1 = __dp4a(q[w], kv.y, s1);
            s2 = __dp4a(q[w], kv.z, s2);
            s3 = __dp4a(q[w], kv.w, s3);
        }
        int a0 = min(127, __float2int_rn(expf((float)s0 * alpha - rmax) * escale));
        int a1 = min(127, __float2int_rn(expf((float)s1 * alpha - rmax) * escale));
        int a2 = min(127, __float2int_rn(expf((float)s2 * alpha - rmax) * escale));
        int a3 = min(127, __float2int_rn(expf((float)s3 * alpha - rmax) * escale));
        s_aq[warp][t * 32 + lane] = a0 | (a1 << 8) | (a2 << 16) | (a3 << 24);
    }
    __syncwarp();

    const int* vb = g_v8t + (size_t)bh * 256 * DH;
    const int* aq = s_aq[warp];
    const float oscale = da * dv;
    #pragma unroll
    for (int dd = 0; dd < 2; dd++) {
        const int d = dd * 32 + lane;
        int acc = 0;
        #pragma unroll 8
        for (int w = 0; w < 256; w++)
            acc = __dp4a(aq[w], vb[w * DH + d], acc);
        g_oattn[((size_t)(b * NQ + row)) * D + h * DH + d] = (float)acc * oscale;
    }
}

// ---------------- launch ----------------
extern "C" void kernel_launch(void* const* d_in, const int* in_sizes, int n_in,
                              void* d_out, int out_size) {
    const float* x   = (const float*)d_in[0];
    const float* ctx = (const float*)d_in[1];
    const float* Wq  = (const float*)d_in[2];
    const float* Wk  = (const float*)d_in[3];
    const float* Wv  = (const float*)d_in[4];
    const float* Wo  = (const float*)d_in[5];
    const float* bo  = (const float*)d_in[6];
    float* out = (float*)d_out;

    void *pq, *pk, *pv, *po;
    cudaGetSymbolAddress(&pq, g_q);
    cudaGetSymbolAddress(&pk, g_k);
    cudaGetSymbolAddress(&pv, g_v);
    cudaGetSymbolAddress(&po, g_oattn);

    init_kernel<<<1, 32>>>();

    // projections (fp32 — precision is load-bearing for quantization buckets)
    gemm128<<<dim3(D / 128, MQ / 128), 256>>>(x,   Wq, nullptr, (float*)pq, MQ, D, D);
    gemm128<<<dim3(D / 128, MK / 128), 256>>>(ctx, Wk, nullptr, (float*)pk, MK, D, DC);
    gemm128<<<dim3(D / 128, MK / 128), 256>>>(ctx, Wv, nullptr, (float*)pv, MK, D, DC);

    // per-tensor abs-max
    absmax_kernel<<<512, 256>>>((const float*)pq, MQ * D, 0);
    absmax_kernel<<<256, 256>>>((const float*)pk, MK * D, 1);
    absmax_kernel<<<256, 256>>>((const float*)pv, MK * D, 2);

    // int8 quantization (layouts tuned for coalesced dp4a streams)
    quant_q_kernel <<<(BH * NQ * 16) / 256, 256>>>();
    quant_kT_kernel<<<(BH * 16 * NK) / 256, 256>>>();
    quant_vT_kernel<<<(BH * 256 * DH) / 256, 256>>>();

    // attention: exact int8 scores, softmax stats + global attn max, then quantized AV
    attn_pass1<<<dim3(NQ / 8, BH), 256>>>();
    attn_pass2<<<dim3(NQ / 8, BH), 256>>>();

    // output projection + bias
    gemm128<<<dim3(D / 128, MQ / 128), 256>>>((const float*)po, Wo, bo, out, MQ, D, D);
}